// round 14
// baseline (speedup 1.0000x reference)
#include <cuda_runtime.h>
#include <math.h>
#include <stdint.h>

// Problem constants (fixed shapes)
#define Bb   2
#define Ll   2048
#define DMd  2048
#define DIi  4096
#define Nst  64
#define Pd   64
#define Hh   64
#define CONVC 4224
#define PROJC 8384
#define EPSf 1e-6f
#define ML   (Bb*Ll)   // 4096 rows

// ---------------- scratch (device globals; no allocation allowed) ----------
__device__ float g_hs[(size_t)ML * DMd];     // rmsnorm(u), tf32-rounded
__device__ float g_zx[(size_t)ML * PROJC];   // in_proj output
__device__ float g_xc[(size_t)ML * CONVC];   // conv+silu output
__device__ float g_dt[ML * Hh];
__device__ float g_dA[ML * Hh];
__device__ float g_y [(size_t)ML * DIi];     // scan output + D*x
__device__ float g_nr[(size_t)ML * DIi];     // gated rmsnorm output, tf32-rounded
__device__ float g_pt[(size_t)4 * ML * DMd]; // split-K partials for out_proj

// ====================== PTX helpers =======================================
__device__ __forceinline__ uint32_t smem_u32(const void* p) {
    uint32_t a;
    asm("{ .reg .u64 t; cvta.to.shared.u64 t, %1; cvt.u32.u64 %0, t; }" : "=r"(a) : "l"(p));
    return a;
}
__device__ __forceinline__ void cp16(uint32_t dst, const void* src, int srcsize) {
    asm volatile("cp.async.cg.shared.global [%0], [%1], 16, %2;" :: "r"(dst), "l"(src), "r"(srcsize));
}
#define CP_COMMIT() asm volatile("cp.async.commit_group;" ::: "memory")
#define CP_WAIT(n)  asm volatile("cp.async.wait_group %0;" :: "n"(n) : "memory")

__device__ __forceinline__ void mma_tf32(float* d, const uint32_t* a, const uint32_t* b) {
    asm volatile(
        "mma.sync.aligned.m16n8k8.row.col.f32.tf32.tf32.f32 "
        "{%0,%1,%2,%3}, {%4,%5,%6,%7}, {%8,%9}, {%0,%1,%2,%3};"
        : "+f"(d[0]), "+f"(d[1]), "+f"(d[2]), "+f"(d[3])
        : "r"(a[0]), "r"(a[1]), "r"(a[2]), "r"(a[3]), "r"(b[0]), "r"(b[1]));
}
__device__ __forceinline__ uint32_t tf32u(float x) {
    uint32_t r; asm("cvt.rna.tf32.f32 %0, %1;" : "=r"(r) : "f"(x));
    return r;
}
__device__ __forceinline__ void ldsm_x4(uint32_t& r0, uint32_t& r1, uint32_t& r2, uint32_t& r3,
                                        uint32_t addr) {
    asm volatile("ldmatrix.sync.aligned.m8n8.x4.shared.b16 {%0,%1,%2,%3}, [%4];"
        : "=r"(r0), "=r"(r1), "=r"(r2), "=r"(r3) : "r"(addr));
}

// ====================== tf32 tensor-core GEMM (mma.sync + ldmatrix) ========
// C[m,n] = sum_{k in [z*kLen,(z+1)*kLen)} A[m,k] * W[n,k] (+res).
// A:(M,K) pre-rounded tf32; W:(N,K) raw fp32, rounded in-register (idempotent).
// CTA 128x128x16, 8 warps, warp tile 64x32 (4x4 m16n8k8), 3-stage cp.async ring.
// Fragments loaded via ldmatrix.x4 (8x8 b16 matrix == 8x4 tf32 tile).
#define BM 128
#define BN 128
#define BK 16
#define KPAD 4
#define KP (BK + KPAD)          // 20 floats row pitch (80 B; all frag rows 16B-aligned)
#define T_STG (BM * KP)          // floats per tile stage (A == B size)
#define SMEM_GEMM (6 * T_STG * 4) // 3 stages x (A + B) = 61440 B

__global__ __launch_bounds__(256, 2) void gemm_mma(
    const float* __restrict__ A, const float* __restrict__ W,
    float* __restrict__ Cbase, const float* __restrict__ res,
    int Nout, int K, int kLen)
{
    extern __shared__ float sm[];
    float* Asm = sm;                 // 3 * T_STG
    float* Bsm = sm + 3 * T_STG;     // 3 * T_STG
    uint32_t sA = smem_u32(Asm);
    uint32_t sB = smem_u32(Bsm);

    int tid = threadIdx.x;
    int warp = tid >> 5, lane = tid & 31;
    int bm = blockIdx.y * BM, bn = blockIdx.x * BN;
    int k0base = blockIdx.z * kLen;
    float* C = Cbase + (size_t)blockIdx.z * ((size_t)ML * Nout);
    int wm = (warp >> 2) * 64;   // warp M offset in tile
    int wn = (warp & 3) * 32;    // warp N offset in tile

    // ldmatrix per-lane source offsets (within a stage buffer, in bytes):
    // A x4 for one mt tile: matrices {rows0-7,k0-3},{rows8-15,k0-3},{rows0-7,k4-7},{rows8-15,k4-7}
    //   lane l -> row (l&15), col-half (l>>4)*4
    uint32_t aLaneOff = (((uint32_t)(wm + (lane & 15)) * KP) + ((lane >> 4) << 2)) * 4;
    // B x4 for one nt-pair: matrices {nt rows,k0-3},{nt rows,k4-7},{nt+1 rows,k0-3},{nt+1 rows,k4-7}
    //   lane l -> row (wn + ((l>>4)&1)*8 + (l&7)), col-half ((l>>3)&1)*4
    uint32_t bLaneOff = (((uint32_t)(wn + (((lane >> 4) & 1) << 3) + (lane & 7)) * KP)
                         + (((lane >> 3) & 1) << 2)) * 4;

    float d[4][4][4];
    #pragma unroll
    for (int i = 0; i < 4; i++)
        #pragma unroll
        for (int j = 0; j < 4; j++)
            #pragma unroll
            for (int f = 0; f < 4; f++) d[i][j][f] = 0.f;

    int NS = kLen / BK;

    // stage loader: 512 cp16 tasks for A, 512 for B -> 4 per thread
    auto load_stage = [&](int s, int buf) {
        int k0 = k0base + s * BK;
        uint32_t aoff = sA + buf * T_STG * 4;
        uint32_t boff = sB + buf * T_STG * 4;
        #pragma unroll
        for (int i = 0; i < 2; i++) {
            int id = tid + i * 256;
            int r = id >> 2, seg = id & 3;
            cp16(aoff + (r * KP + seg * 4) * 4,
                 A + (size_t)(bm + r) * K + k0 + seg * 4, 16);
        }
        #pragma unroll
        for (int i = 0; i < 2; i++) {
            int id = tid + i * 256;
            int r = id >> 2, seg = id & 3;
            int ok = (bn + r) < Nout;
            cp16(boff + (r * KP + seg * 4) * 4,
                 W + (size_t)(ok ? (bn + r) : 0) * K + k0 + seg * 4, ok ? 16 : 0);
        }
        CP_COMMIT();
    };

    auto compute = [&](int buf) {
        uint32_t aBuf = sA + buf * T_STG * 4 + aLaneOff;
        uint32_t bBuf = sB + buf * T_STG * 4 + bLaneOff;
        #pragma unroll
        for (int ks = 0; ks < BK; ks += 8) {
            uint32_t af[4][4], bf[4][2];
            #pragma unroll
            for (int mt = 0; mt < 4; mt++)
                ldsm_x4(af[mt][0], af[mt][1], af[mt][2], af[mt][3],
                        aBuf + (uint32_t)(mt * 16 * KP + ks) * 4);
            #pragma unroll
            for (int np = 0; np < 2; np++)
                ldsm_x4(bf[2*np][0], bf[2*np][1], bf[2*np+1][0], bf[2*np+1][1],
                        bBuf + (uint32_t)(np * 16 * KP + ks) * 4);
            // round W fragments to tf32 (idempotent wrt pre-rounded inputs)
            #pragma unroll
            for (int nt = 0; nt < 4; nt++) {
                bf[nt][0] = tf32u(__uint_as_float(bf[nt][0]));
                bf[nt][1] = tf32u(__uint_as_float(bf[nt][1]));
            }
            #pragma unroll
            for (int mt = 0; mt < 4; mt++)
                #pragma unroll
                for (int nt = 0; nt < 4; nt++)
                    mma_tf32(d[mt][nt], af[mt], bf[nt]);
        }
    };

    load_stage(0, 0);
    load_stage(1, 1);
    for (int s = 0; s < NS; s++) {
        if (s + 1 < NS) { CP_WAIT(1); } else { CP_WAIT(0); }
        __syncthreads();
        if (s + 2 < NS) load_stage(s + 2, (s + 2) % 3);
        compute(s % 3);
    }

    // epilogue
    int row = lane >> 2, kq = lane & 3;
    #pragma unroll
    for (int mt = 0; mt < 4; mt++) {
        int r0 = bm + wm + mt * 16 + row;
        #pragma unroll
        for (int nt = 0; nt < 4; nt++) {
            int c0 = bn + wn + nt * 8 + kq * 2;
            if (c0 < Nout) {
                float2 v0 = make_float2(d[mt][nt][0], d[mt][nt][1]);
                float2 v1 = make_float2(d[mt][nt][2], d[mt][nt][3]);
                if (res) {
                    float2 q0 = *(const float2*)(res + (size_t)r0 * Nout + c0);
                    float2 q1 = *(const float2*)(res + (size_t)(r0 + 8) * Nout + c0);
                    v0.x += q0.x; v0.y += q0.y;
                    v1.x += q1.x; v1.y += q1.y;
                }
                *(float2*)(C + (size_t)r0 * Nout + c0) = v0;
                *(float2*)(C + (size_t)(r0 + 8) * Nout + c0) = v1;
            }
        }
    }
}

// ---------------- split-K reduce + residual --------------------------------
__global__ void reduce4_kernel(const float* __restrict__ u, float* __restrict__ out) {
    int i = blockIdx.x * 256 + threadIdx.x;   // < ML*DMd/4
    const float4* p0 = (const float4*)g_pt;
    const float4* p1 = p0 + (size_t)ML * DMd / 4;
    const float4* p2 = p1 + (size_t)ML * DMd / 4;
    const float4* p3 = p2 + (size_t)ML * DMd / 4;
    float4 a = p0[i], b = p1[i], c = p2[i], e = p3[i];
    float4 r = ((const float4*)u)[i];
    float4 o;
    o.x = a.x + b.x + c.x + e.x + r.x;
    o.y = a.y + b.y + c.y + e.y + r.y;
    o.z = a.z + b.z + c.z + e.z + r.z;
    o.w = a.w + b.w + c.w + e.w + r.w;
    ((float4*)out)[i] = o;
}

// ---------------- helpers ----------------
__device__ __forceinline__ float block_sum_256(float v) {
    #pragma unroll
    for (int o = 16; o; o >>= 1) v += __shfl_xor_sync(0xffffffffu, v, o);
    __shared__ float sh[8];
    int w = threadIdx.x >> 5;
    if ((threadIdx.x & 31) == 0) sh[w] = v;
    __syncthreads();
    float s = 0.f;
    #pragma unroll
    for (int i = 0; i < 8; i++) s += sh[i];
    return s;
}
__device__ __forceinline__ float siluf(float x) { return x / (1.f + expf(-x)); }
__device__ __forceinline__ float tf32r(float x) {
    return __uint_as_float(tf32u(x));
}

// ---------------- 1) input RMSNorm: u (ML,2048) -> g_hs (tf32) -------------
__global__ void rmsnorm_in_kernel(const float* __restrict__ u,
                                  const float* __restrict__ w) {
    int row = blockIdx.x;
    const float* x = u + (size_t)row * DMd;
    float* o = g_hs + (size_t)row * DMd;
    int t = threadIdx.x;
    float v[8];
    float ss = 0.f;
    #pragma unroll
    for (int i = 0; i < 2; i++) {
        float4 p = *(const float4*)(x + t * 4 + i * 1024);
        v[i*4+0]=p.x; v[i*4+1]=p.y; v[i*4+2]=p.z; v[i*4+3]=p.w;
        ss += p.x*p.x + p.y*p.y + p.z*p.z + p.w*p.w;
    }
    float total = block_sum_256(ss);
    float scale = rsqrtf(total / (float)DMd + EPSf);
    #pragma unroll
    for (int i = 0; i < 2; i++) {
        int c = t * 4 + i * 1024;
        float4 q;
        q.x = tf32r(w[c+0] * v[i*4+0] * scale);
        q.y = tf32r(w[c+1] * v[i*4+1] * scale);
        q.z = tf32r(w[c+2] * v[i*4+2] * scale);
        q.w = tf32r(w[c+3] * v[i*4+3] * scale);
        *(float4*)(o + c) = q;
    }
}

// ---------------- 3) causal depthwise conv (K=4) + SiLU --------------------
__global__ void conv_silu_kernel(const float* __restrict__ conv_w,
                                 const float* __restrict__ conv_b) {
    int c  = blockIdx.x * 128 + threadIdx.x;   // 0..4223
    int bl = blockIdx.y;                        // 0..ML-1
    int b = bl >> 11;
    int l = bl & 2047;
    float acc = conv_b[c];
    #pragma unroll
    for (int k = 0; k < 4; k++) {
        int ls = l + k - 3;
        if (ls >= 0)
            acc += g_zx[(size_t)((b << 11) + ls) * PROJC + DIi + c] * conv_w[k * CONVC + c];
    }
    g_xc[(size_t)bl * CONVC + c] = siluf(acc);
}

// ---------------- 4) dt = softplus(raw + bias); dA = exp(-exp(Alog)*dt) ----
__global__ void dt_kernel(const float* __restrict__ dt_bias,
                          const float* __restrict__ A_log) {
    int idx = blockIdx.x * 256 + threadIdx.x;
    int m = idx >> 6;
    int h = idx & 63;
    float x = g_zx[(size_t)m * PROJC + DIi + CONVC + h] + dt_bias[h];
    float sp = (x > 20.f) ? x : log1pf(expf(x));
    g_dt[idx] = sp;
    g_dA[idx] = expf(-expf(A_log[h]) * sp);
}

// ---------------- 5) sequential selective scan (512 thr: 8 n/thread) -------
__global__ __launch_bounds__(512) void scan_kernel(const float* __restrict__ Dp) {
    int hh = blockIdx.x, b = blockIdx.y;
    int tid = threadIdx.x;
    int q = tid & 7;         // 0..7
    int p = tid >> 3;        // 0..63
    int n0 = q << 3;         // 8 n's per thread

    __shared__ float sB[32][64], sC[32][64], sx[32][64];
    __shared__ float sdt[32], sdA[32];

    float h[8];
    #pragma unroll
    for (int i = 0; i < 8; i++) h[i] = 0.f;
    float Dh = Dp[hh];

    for (int l0 = 0; l0 < Ll; l0 += 32) {
        __syncthreads();
        for (int j = tid; j < 32 * 64; j += 512) {
            int s = j >> 6, n = j & 63;
            size_t rb = (size_t)((b << 11) + l0 + s) * CONVC;
            sB[s][n] = g_xc[rb + DIi + n];
            sC[s][n] = g_xc[rb + DIi + Nst + n];
            sx[s][n] = g_xc[rb + (hh << 6) + n];
        }
        if (tid < 32) {
            int m = (b << 11) + l0 + tid;
            sdt[tid] = g_dt[m * Hh + hh];
            sdA[tid] = g_dA[m * Hh + hh];
        }
        __syncthreads();

        for (int s = 0; s < 32; s++) {
            float dAv = sdA[s], dtv = sdt[s];
            float x = sx[s][p];
            float dtx = dtv * x;
            float4 Bv0 = *(const float4*)&sB[s][n0];
            float4 Bv1 = *(const float4*)&sB[s][n0 + 4];
            float4 Cv0 = *(const float4*)&sC[s][n0];
            float4 Cv1 = *(const float4*)&sC[s][n0 + 4];
            float a0, a1;
            h[0] = dAv*h[0] + dtx*Bv0.x; a0  = h[0]*Cv0.x;
            h[1] = dAv*h[1] + dtx*Bv0.y; a0 += h[1]*Cv0.y;
            h[2] = dAv*h[2] + dtx*Bv0.z; a0 += h[2]*Cv0.z;
            h[3] = dAv*h[3] + dtx*Bv0.w; a0 += h[3]*Cv0.w;
            h[4] = dAv*h[4] + dtx*Bv1.x; a1  = h[4]*Cv1.x;
            h[5] = dAv*h[5] + dtx*Bv1.y; a1 += h[5]*Cv1.y;
            h[6] = dAv*h[6] + dtx*Bv1.z; a1 += h[6]*Cv1.z;
            h[7] = dAv*h[7] + dtx*Bv1.w; a1 += h[7]*Cv1.w;
            float a = a0 + a1;
            a += __shfl_xor_sync(0xffffffffu, a, 1);
            a += __shfl_xor_sync(0xffffffffu, a, 2);
            a += __shfl_xor_sync(0xffffffffu, a, 4);
            if (q == 0) {
                size_t ob = (size_t)((b << 11) + l0 + s) * DIi + (hh << 6);
                g_y[ob + p] = a + Dh * x;
            }
        }
    }
}

// ---------------- 6) gated RMSNorm -> g_nr (tf32) --------------------------
__global__ void gated_norm_kernel(const float* __restrict__ nw) {
    int row = blockIdx.x;
    const float* yr = g_y + (size_t)row * DIi;
    const float* zr = g_zx + (size_t)row * PROJC;
    float* o = g_nr + (size_t)row * DIi;
    int t = threadIdx.x;
    float v[16];
    float ss = 0.f;
    #pragma unroll
    for (int i = 0; i < 4; i++) {
        int c = t * 4 + i * 1024;
        float4 yv = *(const float4*)(yr + c);
        float4 zv = *(const float4*)(zr + c);
        float a0 = yv.x * siluf(zv.x);
        float a1 = yv.y * siluf(zv.y);
        float a2 = yv.z * siluf(zv.z);
        float a3 = yv.w * siluf(zv.w);
        v[i*4+0]=a0; v[i*4+1]=a1; v[i*4+2]=a2; v[i*4+3]=a3;
        ss += a0*a0 + a1*a1 + a2*a2 + a3*a3;
    }
    float total = block_sum_256(ss);
    float scale = rsqrtf(total / (float)DIi + EPSf);
    #pragma unroll
    for (int i = 0; i < 4; i++) {
        int c = t * 4 + i * 1024;
        float4 qv;
        qv.x = tf32r(nw[c+0] * v[i*4+0] * scale);
        qv.y = tf32r(nw[c+1] * v[i*4+1] * scale);
        qv.z = tf32r(nw[c+2] * v[i*4+2] * scale);
        qv.w = tf32r(nw[c+3] * v[i*4+3] * scale);
        *(float4*)(o + c) = qv;
    }
}

// ---------------- launcher -------------------------------------------------
extern "C" void kernel_launch(void* const* d_in, const int* in_sizes, int n_in,
                              void* d_out, int out_size) {
    const float* u          = (const float*)d_in[0];
    const float* ln_w       = (const float*)d_in[1];
    const float* in_proj_w  = (const float*)d_in[2];
    const float* conv_w     = (const float*)d_in[3];
    const float* conv_b     = (const float*)d_in[4];
    const float* dt_bias    = (const float*)d_in[5];
    const float* A_log      = (const float*)d_in[6];
    const float* Dp         = (const float*)d_in[7];
    const float* norm_w     = (const float*)d_in[8];
    const float* out_proj_w = (const float*)d_in[9];
    float* out = (float*)d_out;

    float *hs_p, *zx_p, *nr_p, *pt_p;
    cudaGetSymbolAddress((void**)&hs_p, g_hs);
    cudaGetSymbolAddress((void**)&zx_p, g_zx);
    cudaGetSymbolAddress((void**)&nr_p, g_nr);
    cudaGetSymbolAddress((void**)&pt_p, g_pt);

    cudaFuncSetAttribute(gemm_mma, cudaFuncAttributeMaxDynamicSharedMemorySize, SMEM_GEMM);

    // 1) input rmsnorm (tf32-rounded output)
    rmsnorm_in_kernel<<<ML, 256>>>(u, ln_w);

    // 2) in_proj: (4096,2048) x (8384,2048)^T -> (4096,8384); W rounded in-kernel
    {
        dim3 grid((PROJC + BN - 1) / BN, ML / BM, 1);
        gemm_mma<<<grid, 256, SMEM_GEMM>>>(hs_p, in_proj_w, zx_p, nullptr, PROJC, DMd, DMd);
    }

    // 3) conv + silu
    {
        dim3 grid(CONVC / 128, ML);
        conv_silu_kernel<<<grid, 128>>>(conv_w, conv_b);
    }

    // 4) dt / dA
    dt_kernel<<<(ML * Hh) / 256, 256>>>(dt_bias, A_log);

    // 5) scan (512 threads, 8 n per thread)
    {
        dim3 grid(Hh, Bb);
        scan_kernel<<<grid, 512>>>(Dp);
    }

    // 6) gated rmsnorm (tf32-rounded output)
    gated_norm_kernel<<<ML, 256>>>(norm_w);

    // 7) out_proj split-K=4: (4096,4096) x (2048,4096)^T -> 4 partials
    {
        dim3 grid(DMd / BN, ML / BM, 4);
        gemm_mma<<<grid, 256, SMEM_GEMM>>>(nr_p, out_proj_w, pt_p, nullptr, DMd, DIi, DIi / 4);
    }

    // 8) reduce partials + residual -> out
    reduce4_kernel<<<(ML * DMd / 4) / 256, 256>>>(u, out);
}

// round 16
// speedup vs baseline: 1.1074x; 1.1074x over previous
#include <cuda_runtime.h>
#include <math.h>
#include <stdint.h>

// Problem constants (fixed shapes)
#define Bb   2
#define Ll   2048
#define DMd  2048
#define DIi  4096
#define Nst  64
#define Pd   64
#define Hh   64
#define CONVC 4224
#define PROJC 8384
#define EPSf 1e-6f
#define ML   (Bb*Ll)   // 4096 rows

// ---------------- scratch (device globals; no allocation allowed) ----------
__device__ float g_hs[(size_t)ML * DMd];     // rmsnorm(u), tf32-rounded
__device__ float g_zx[(size_t)ML * PROJC];   // in_proj output
__device__ float g_xc[(size_t)ML * CONVC];   // conv+silu output
__device__ float g_dt[ML * Hh];
__device__ float g_dA[ML * Hh];
__device__ float g_y [(size_t)ML * DIi];     // scan output + D*x
__device__ float g_nr[(size_t)ML * DIi];     // gated rmsnorm output, tf32-rounded
__device__ float g_pt[(size_t)4 * ML * DMd]; // split-K partials for out_proj

// ====================== PTX helpers =======================================
__device__ __forceinline__ uint32_t smem_u32(const void* p) {
    uint32_t a;
    asm("{ .reg .u64 t; cvta.to.shared.u64 t, %1; cvt.u32.u64 %0, t; }" : "=r"(a) : "l"(p));
    return a;
}
__device__ __forceinline__ void cp16(uint32_t dst, const void* src, int srcsize) {
    asm volatile("cp.async.cg.shared.global [%0], [%1], 16, %2;" :: "r"(dst), "l"(src), "r"(srcsize));
}
#define CP_COMMIT() asm volatile("cp.async.commit_group;" ::: "memory")
#define CP_WAIT(n)  asm volatile("cp.async.wait_group %0;" :: "n"(n) : "memory")

__device__ __forceinline__ void mma_tf32(float* d, const uint32_t* a, const uint32_t* b) {
    asm volatile(
        "mma.sync.aligned.m16n8k8.row.col.f32.tf32.tf32.f32 "
        "{%0,%1,%2,%3}, {%4,%5,%6,%7}, {%8,%9}, {%0,%1,%2,%3};"
        : "+f"(d[0]), "+f"(d[1]), "+f"(d[2]), "+f"(d[3])
        : "r"(a[0]), "r"(a[1]), "r"(a[2]), "r"(a[3]), "r"(b[0]), "r"(b[1]));
}
__device__ __forceinline__ uint32_t tf32u(float x) {
    uint32_t r; asm("cvt.rna.tf32.f32 %0, %1;" : "=r"(r) : "f"(x));
    return r;
}
__device__ __forceinline__ void ldsm_x4(uint32_t& r0, uint32_t& r1, uint32_t& r2, uint32_t& r3,
                                        uint32_t addr) {
    asm volatile("ldmatrix.sync.aligned.m8n8.x4.shared.b16 {%0,%1,%2,%3}, [%4];"
        : "=r"(r0), "=r"(r1), "=r"(r2), "=r"(r3) : "r"(addr));
}

// ====================== tf32 tensor-core GEMM (mma.sync + ldmatrix) ========
// C[m,n] = sum_{k in [z*kLen,(z+1)*kLen)} A[m,k] * W[n,k] (+res).
// A:(M,K) pre-rounded tf32; W:(N,K) raw fp32, rounded in-register (idempotent).
// CTA 128x128x32, 8 warps, warp tile 64x32 (4x4 m16n8k8), 2-stage cp.async
// double buffer. BK=32 -> 64 contiguous MMAs/warp between barriers.
#define BM 128
#define BN 128
#define BK 32
#define KPAD 4
#define KP (BK + KPAD)           // 36 floats row pitch (144 B; 16B-aligned rows)
#define T_STG (BM * KP)           // floats per tile stage (A == B size)
#define SMEM_GEMM (4 * T_STG * 4) // 2 stages x (A + B) = 73728 B

__global__ __launch_bounds__(256, 2) void gemm_mma(
    const float* __restrict__ A, const float* __restrict__ W,
    float* __restrict__ Cbase, const float* __restrict__ res,
    int Nout, int K, int kLen)
{
    extern __shared__ float sm[];
    float* Asm = sm;                 // 2 * T_STG
    float* Bsm = sm + 2 * T_STG;     // 2 * T_STG
    uint32_t sA = smem_u32(Asm);
    uint32_t sB = smem_u32(Bsm);

    int tid = threadIdx.x;
    int warp = tid >> 5, lane = tid & 31;
    int bm = blockIdx.y * BM, bn = blockIdx.x * BN;
    int k0base = blockIdx.z * kLen;
    float* C = Cbase + (size_t)blockIdx.z * ((size_t)ML * Nout);
    int wm = (warp >> 2) * 64;   // warp M offset in tile
    int wn = (warp & 3) * 32;    // warp N offset in tile

    // ldmatrix per-lane source offsets (within a stage buffer, in bytes)
    uint32_t aLaneOff = (((uint32_t)(wm + (lane & 15)) * KP) + ((lane >> 4) << 2)) * 4;
    uint32_t bLaneOff = (((uint32_t)(wn + (((lane >> 4) & 1) << 3) + (lane & 7)) * KP)
                         + (((lane >> 3) & 1) << 2)) * 4;

    float d[4][4][4];
    #pragma unroll
    for (int i = 0; i < 4; i++)
        #pragma unroll
        for (int j = 0; j < 4; j++)
            #pragma unroll
            for (int f = 0; f < 4; f++) d[i][j][f] = 0.f;

    int NS = kLen / BK;

    // stage loader: 1024 cp16 tasks for A, 1024 for B -> 8 per thread
    auto load_stage = [&](int s, int buf) {
        int k0 = k0base + s * BK;
        uint32_t aoff = sA + buf * T_STG * 4;
        uint32_t boff = sB + buf * T_STG * 4;
        #pragma unroll
        for (int i = 0; i < 4; i++) {
            int id = tid + i * 256;
            int r = id >> 3, seg = id & 7;
            cp16(aoff + (r * KP + seg * 4) * 4,
                 A + (size_t)(bm + r) * K + k0 + seg * 4, 16);
        }
        #pragma unroll
        for (int i = 0; i < 4; i++) {
            int id = tid + i * 256;
            int r = id >> 3, seg = id & 7;
            int ok = (bn + r) < Nout;
            cp16(boff + (r * KP + seg * 4) * 4,
                 W + (size_t)(ok ? (bn + r) : 0) * K + k0 + seg * 4, ok ? 16 : 0);
        }
        CP_COMMIT();
    };

    auto compute = [&](int buf) {
        uint32_t aBuf = sA + buf * T_STG * 4 + aLaneOff;
        uint32_t bBuf = sB + buf * T_STG * 4 + bLaneOff;
        #pragma unroll
        for (int ks = 0; ks < BK; ks += 8) {
            uint32_t af[4][4], bf[4][2];
            #pragma unroll
            for (int mt = 0; mt < 4; mt++)
                ldsm_x4(af[mt][0], af[mt][1], af[mt][2], af[mt][3],
                        aBuf + (uint32_t)(mt * 16 * KP + ks) * 4);
            #pragma unroll
            for (int np = 0; np < 2; np++)
                ldsm_x4(bf[2*np][0], bf[2*np][1], bf[2*np+1][0], bf[2*np+1][1],
                        bBuf + (uint32_t)(np * 16 * KP + ks) * 4);
            // round W fragments to tf32 (idempotent wrt pre-rounded inputs)
            #pragma unroll
            for (int nt = 0; nt < 4; nt++) {
                bf[nt][0] = tf32u(__uint_as_float(bf[nt][0]));
                bf[nt][1] = tf32u(__uint_as_float(bf[nt][1]));
            }
            #pragma unroll
            for (int mt = 0; mt < 4; mt++)
                #pragma unroll
                for (int nt = 0; nt < 4; nt++)
                    mma_tf32(d[mt][nt], af[mt], bf[nt]);
        }
    };

    load_stage(0, 0);
    for (int s = 0; s < NS; s++) {
        int buf = s & 1;
        if (s + 1 < NS) {
            load_stage(s + 1, buf ^ 1);
            CP_WAIT(1);
        } else {
            CP_WAIT(0);
        }
        __syncthreads();
        compute(buf);
        __syncthreads();
    }

    // epilogue
    int row = lane >> 2, kq = lane & 3;
    #pragma unroll
    for (int mt = 0; mt < 4; mt++) {
        int r0 = bm + wm + mt * 16 + row;
        #pragma unroll
        for (int nt = 0; nt < 4; nt++) {
            int c0 = bn + wn + nt * 8 + kq * 2;
            if (c0 < Nout) {
                float2 v0 = make_float2(d[mt][nt][0], d[mt][nt][1]);
                float2 v1 = make_float2(d[mt][nt][2], d[mt][nt][3]);
                if (res) {
                    float2 q0 = *(const float2*)(res + (size_t)r0 * Nout + c0);
                    float2 q1 = *(const float2*)(res + (size_t)(r0 + 8) * Nout + c0);
                    v0.x += q0.x; v0.y += q0.y;
                    v1.x += q1.x; v1.y += q1.y;
                }
                *(float2*)(C + (size_t)r0 * Nout + c0) = v0;
                *(float2*)(C + (size_t)(r0 + 8) * Nout + c0) = v1;
            }
        }
    }
}

// ---------------- split-K reduce + residual --------------------------------
__global__ void reduce4_kernel(const float* __restrict__ u, float* __restrict__ out) {
    int i = blockIdx.x * 256 + threadIdx.x;   // < ML*DMd/4
    const float4* p0 = (const float4*)g_pt;
    const float4* p1 = p0 + (size_t)ML * DMd / 4;
    const float4* p2 = p1 + (size_t)ML * DMd / 4;
    const float4* p3 = p2 + (size_t)ML * DMd / 4;
    float4 a = p0[i], b = p1[i], c = p2[i], e = p3[i];
    float4 r = ((const float4*)u)[i];
    float4 o;
    o.x = a.x + b.x + c.x + e.x + r.x;
    o.y = a.y + b.y + c.y + e.y + r.y;
    o.z = a.z + b.z + c.z + e.z + r.z;
    o.w = a.w + b.w + c.w + e.w + r.w;
    ((float4*)out)[i] = o;
}

// ---------------- helpers ----------------
__device__ __forceinline__ float block_sum_256(float v) {
    #pragma unroll
    for (int o = 16; o; o >>= 1) v += __shfl_xor_sync(0xffffffffu, v, o);
    __shared__ float sh[8];
    int w = threadIdx.x >> 5;
    if ((threadIdx.x & 31) == 0) sh[w] = v;
    __syncthreads();
    float s = 0.f;
    #pragma unroll
    for (int i = 0; i < 8; i++) s += sh[i];
    return s;
}
__device__ __forceinline__ float siluf(float x) { return x / (1.f + expf(-x)); }
__device__ __forceinline__ float tf32r(float x) {
    return __uint_as_float(tf32u(x));
}

// ---------------- 1) input RMSNorm: u (ML,2048) -> g_hs (tf32) -------------
__global__ void rmsnorm_in_kernel(const float* __restrict__ u,
                                  const float* __restrict__ w) {
    int row = blockIdx.x;
    const float* x = u + (size_t)row * DMd;
    float* o = g_hs + (size_t)row * DMd;
    int t = threadIdx.x;
    float v[8];
    float ss = 0.f;
    #pragma unroll
    for (int i = 0; i < 2; i++) {
        float4 p = *(const float4*)(x + t * 4 + i * 1024);
        v[i*4+0]=p.x; v[i*4+1]=p.y; v[i*4+2]=p.z; v[i*4+3]=p.w;
        ss += p.x*p.x + p.y*p.y + p.z*p.z + p.w*p.w;
    }
    float total = block_sum_256(ss);
    float scale = rsqrtf(total / (float)DMd + EPSf);
    #pragma unroll
    for (int i = 0; i < 2; i++) {
        int c = t * 4 + i * 1024;
        float4 q;
        q.x = tf32r(w[c+0] * v[i*4+0] * scale);
        q.y = tf32r(w[c+1] * v[i*4+1] * scale);
        q.z = tf32r(w[c+2] * v[i*4+2] * scale);
        q.w = tf32r(w[c+3] * v[i*4+3] * scale);
        *(float4*)(o + c) = q;
    }
}

// ---------------- 3) causal depthwise conv (K=4) + SiLU --------------------
__global__ void conv_silu_kernel(const float* __restrict__ conv_w,
                                 const float* __restrict__ conv_b) {
    int c  = blockIdx.x * 128 + threadIdx.x;   // 0..4223
    int bl = blockIdx.y;                        // 0..ML-1
    int b = bl >> 11;
    int l = bl & 2047;
    float acc = conv_b[c];
    #pragma unroll
    for (int k = 0; k < 4; k++) {
        int ls = l + k - 3;
        if (ls >= 0)
            acc += g_zx[(size_t)((b << 11) + ls) * PROJC + DIi + c] * conv_w[k * CONVC + c];
    }
    g_xc[(size_t)bl * CONVC + c] = siluf(acc);
}

// ---------------- 4) dt = softplus(raw + bias); dA = exp(-exp(Alog)*dt) ----
__global__ void dt_kernel(const float* __restrict__ dt_bias,
                          const float* __restrict__ A_log) {
    int idx = blockIdx.x * 256 + threadIdx.x;
    int m = idx >> 6;
    int h = idx & 63;
    float x = g_zx[(size_t)m * PROJC + DIi + CONVC + h] + dt_bias[h];
    float sp = (x > 20.f) ? x : log1pf(expf(x));
    g_dt[idx] = sp;
    g_dA[idx] = expf(-expf(A_log[h]) * sp);
}

// ---------------- 5) sequential selective scan (512 thr: 8 n/thread) -------
__global__ __launch_bounds__(512) void scan_kernel(const float* __restrict__ Dp) {
    int hh = blockIdx.x, b = blockIdx.y;
    int tid = threadIdx.x;
    int q = tid & 7;         // 0..7
    int p = tid >> 3;        // 0..63
    int n0 = q << 3;         // 8 n's per thread

    __shared__ float sB[32][64], sC[32][64], sx[32][64];
    __shared__ float sdt[32], sdA[32];

    float h[8];
    #pragma unroll
    for (int i = 0; i < 8; i++) h[i] = 0.f;
    float Dh = Dp[hh];

    for (int l0 = 0; l0 < Ll; l0 += 32) {
        __syncthreads();
        for (int j = tid; j < 32 * 64; j += 512) {
            int s = j >> 6, n = j & 63;
            size_t rb = (size_t)((b << 11) + l0 + s) * CONVC;
            sB[s][n] = g_xc[rb + DIi + n];
            sC[s][n] = g_xc[rb + DIi + Nst + n];
            sx[s][n] = g_xc[rb + (hh << 6) + n];
        }
        if (tid < 32) {
            int m = (b << 11) + l0 + tid;
            sdt[tid] = g_dt[m * Hh + hh];
            sdA[tid] = g_dA[m * Hh + hh];
        }
        __syncthreads();

        for (int s = 0; s < 32; s++) {
            float dAv = sdA[s], dtv = sdt[s];
            float x = sx[s][p];
            float dtx = dtv * x;
            float4 Bv0 = *(const float4*)&sB[s][n0];
            float4 Bv1 = *(const float4*)&sB[s][n0 + 4];
            float4 Cv0 = *(const float4*)&sC[s][n0];
            float4 Cv1 = *(const float4*)&sC[s][n0 + 4];
            float a0, a1;
            h[0] = dAv*h[0] + dtx*Bv0.x; a0  = h[0]*Cv0.x;
            h[1] = dAv*h[1] + dtx*Bv0.y; a0 += h[1]*Cv0.y;
            h[2] = dAv*h[2] + dtx*Bv0.z; a0 += h[2]*Cv0.z;
            h[3] = dAv*h[3] + dtx*Bv0.w; a0 += h[3]*Cv0.w;
            h[4] = dAv*h[4] + dtx*Bv1.x; a1  = h[4]*Cv1.x;
            h[5] = dAv*h[5] + dtx*Bv1.y; a1 += h[5]*Cv1.y;
            h[6] = dAv*h[6] + dtx*Bv1.z; a1 += h[6]*Cv1.z;
            h[7] = dAv*h[7] + dtx*Bv1.w; a1 += h[7]*Cv1.w;
            float a = a0 + a1;
            a += __shfl_xor_sync(0xffffffffu, a, 1);
            a += __shfl_xor_sync(0xffffffffu, a, 2);
            a += __shfl_xor_sync(0xffffffffu, a, 4);
            if (q == 0) {
                size_t ob = (size_t)((b << 11) + l0 + s) * DIi + (hh << 6);
                g_y[ob + p] = a + Dh * x;
            }
        }
    }
}

// ---------------- 6) gated RMSNorm -> g_nr (tf32) --------------------------
__global__ void gated_norm_kernel(const float* __restrict__ nw) {
    int row = blockIdx.x;
    const float* yr = g_y + (size_t)row * DIi;
    const float* zr = g_zx + (size_t)row * PROJC;
    float* o = g_nr + (size_t)row * DIi;
    int t = threadIdx.x;
    float v[16];
    float ss = 0.f;
    #pragma unroll
    for (int i = 0; i < 4; i++) {
        int c = t * 4 + i * 1024;
        float4 yv = *(const float4*)(yr + c);
        float4 zv = *(const float4*)(zr + c);
        float a0 = yv.x * siluf(zv.x);
        float a1 = yv.y * siluf(zv.y);
        float a2 = yv.z * siluf(zv.z);
        float a3 = yv.w * siluf(zv.w);
        v[i*4+0]=a0; v[i*4+1]=a1; v[i*4+2]=a2; v[i*4+3]=a3;
        ss += a0*a0 + a1*a1 + a2*a2 + a3*a3;
    }
    float total = block_sum_256(ss);
    float scale = rsqrtf(total / (float)DIi + EPSf);
    #pragma unroll
    for (int i = 0; i < 4; i++) {
        int c = t * 4 + i * 1024;
        float4 qv;
        qv.x = tf32r(nw[c+0] * v[i*4+0] * scale);
        qv.y = tf32r(nw[c+1] * v[i*4+1] * scale);
        qv.z = tf32r(nw[c+2] * v[i*4+2] * scale);
        qv.w = tf32r(nw[c+3] * v[i*4+3] * scale);
        *(float4*)(o + c) = qv;
    }
}

// ---------------- launcher -------------------------------------------------
extern "C" void kernel_launch(void* const* d_in, const int* in_sizes, int n_in,
                              void* d_out, int out_size) {
    const float* u          = (const float*)d_in[0];
    const float* ln_w       = (const float*)d_in[1];
    const float* in_proj_w  = (const float*)d_in[2];
    const float* conv_w     = (const float*)d_in[3];
    const float* conv_b     = (const float*)d_in[4];
    const float* dt_bias    = (const float*)d_in[5];
    const float* A_log      = (const float*)d_in[6];
    const float* Dp         = (const float*)d_in[7];
    const float* norm_w     = (const float*)d_in[8];
    const float* out_proj_w = (const float*)d_in[9];
    float* out = (float*)d_out;

    float *hs_p, *zx_p, *nr_p, *pt_p;
    cudaGetSymbolAddress((void**)&hs_p, g_hs);
    cudaGetSymbolAddress((void**)&zx_p, g_zx);
    cudaGetSymbolAddress((void**)&nr_p, g_nr);
    cudaGetSymbolAddress((void**)&pt_p, g_pt);

    cudaFuncSetAttribute(gemm_mma, cudaFuncAttributeMaxDynamicSharedMemorySize, SMEM_GEMM);

    // 1) input rmsnorm (tf32-rounded output)
    rmsnorm_in_kernel<<<ML, 256>>>(u, ln_w);

    // 2) in_proj: (4096,2048) x (8384,2048)^T -> (4096,8384); W rounded in-kernel
    {
        dim3 grid((PROJC + BN - 1) / BN, ML / BM, 1);
        gemm_mma<<<grid, 256, SMEM_GEMM>>>(hs_p, in_proj_w, zx_p, nullptr, PROJC, DMd, DMd);
    }

    // 3) conv + silu
    {
        dim3 grid(CONVC / 128, ML);
        conv_silu_kernel<<<grid, 128>>>(conv_w, conv_b);
    }

    // 4) dt / dA
    dt_kernel<<<(ML * Hh) / 256, 256>>>(dt_bias, A_log);

    // 5) scan (512 threads, 8 n per thread)
    {
        dim3 grid(Hh, Bb);
        scan_kernel<<<grid, 512>>>(Dp);
    }

    // 6) gated rmsnorm (tf32-rounded output)
    gated_norm_kernel<<<ML, 256>>>(norm_w);

    // 7) out_proj split-K=4: (4096,4096) x (2048,4096)^T -> 4 partials
    {
        dim3 grid(DMd / BN, ML / BM, 4);
        gemm_mma<<<grid, 256, SMEM_GEMM>>>(nr_p, out_proj_w, pt_p, nullptr, DMd, DIi, DIi / 4);
    }

    // 8) reduce partials + residual -> out
    reduce4_kernel<<<(ML * DMd / 4) / 256, 256>>>(u, out);
}

// round 17
// speedup vs baseline: 1.1175x; 1.0091x over previous
#include <cuda_runtime.h>
#include <math.h>
#include <stdint.h>

// Problem constants (fixed shapes)
#define Bb   2
#define Ll   2048
#define DMd  2048
#define DIi  4096
#define Nst  64
#define Pd   64
#define Hh   64
#define CONVC 4224
#define PROJC 8384
#define EPSf 1e-6f
#define ML   (Bb*Ll)   // 4096 rows

// ---------------- scratch (device globals; no allocation allowed) ----------
__device__ float g_hs[(size_t)ML * DMd];     // rmsnorm(u), tf32-rounded
__device__ float g_zx[(size_t)ML * PROJC];   // in_proj output
__device__ float g_xc[(size_t)ML * CONVC];   // conv+silu output
__device__ float g_dt[ML * Hh];
__device__ float g_dA[ML * Hh];
__device__ float g_y [(size_t)ML * DIi];     // scan output + D*x
__device__ float g_nr[(size_t)ML * DIi];     // gated rmsnorm output, tf32-rounded
__device__ float g_pt[(size_t)4 * ML * DMd]; // split-K partials for out_proj

// ====================== PTX helpers =======================================
__device__ __forceinline__ uint32_t smem_u32(const void* p) {
    uint32_t a;
    asm("{ .reg .u64 t; cvta.to.shared.u64 t, %1; cvt.u32.u64 %0, t; }" : "=r"(a) : "l"(p));
    return a;
}
__device__ __forceinline__ void cp16(uint32_t dst, const void* src, int srcsize) {
    asm volatile("cp.async.cg.shared.global [%0], [%1], 16, %2;" :: "r"(dst), "l"(src), "r"(srcsize));
}
#define CP_COMMIT() asm volatile("cp.async.commit_group;" ::: "memory")
#define CP_WAIT(n)  asm volatile("cp.async.wait_group %0;" :: "n"(n) : "memory")

__device__ __forceinline__ void mma_tf32(float* d, const uint32_t* a, const uint32_t* b) {
    asm volatile(
        "mma.sync.aligned.m16n8k8.row.col.f32.tf32.tf32.f32 "
        "{%0,%1,%2,%3}, {%4,%5,%6,%7}, {%8,%9}, {%0,%1,%2,%3};"
        : "+f"(d[0]), "+f"(d[1]), "+f"(d[2]), "+f"(d[3])
        : "r"(a[0]), "r"(a[1]), "r"(a[2]), "r"(a[3]), "r"(b[0]), "r"(b[1]));
}
__device__ __forceinline__ uint32_t tf32u(float x) {
    uint32_t r; asm("cvt.rna.tf32.f32 %0, %1;" : "=r"(r) : "f"(x));
    return r;
}
__device__ __forceinline__ void ldsm_x4(uint32_t& r0, uint32_t& r1, uint32_t& r2, uint32_t& r3,
                                        uint32_t addr) {
    asm volatile("ldmatrix.sync.aligned.m8n8.x4.shared.b16 {%0,%1,%2,%3}, [%4];"
        : "=r"(r0), "=r"(r1), "=r"(r2), "=r"(r3) : "r"(addr));
}

// ====================== tf32 tensor-core GEMM (mma.sync + ldmatrix) ========
// C[m,n] = sum_{k in [z*kLen,(z+1)*kLen)} A[m,k] * W[n,k] (+res).
// A:(M,K) pre-rounded tf32; W:(N,K) raw fp32, rounded in-register (idempotent).
// CTA 128x128x32, 8 warps, warp tile 64x32 (4x4 m16n8k8).
// 3-stage cp.async ring, ONE __syncthreads per stage. BK=32.
#define BM 128
#define BN 128
#define BK 32
#define KPAD 4
#define KP (BK + KPAD)           // 36 floats row pitch (144 B; 16B-aligned rows)
#define T_STG (BM * KP)           // floats per tile stage (A == B size)
#define SMEM_GEMM (6 * T_STG * 4) // 3 stages x (A + B) = 110592 B (occ 2 kept)

__global__ __launch_bounds__(256, 2) void gemm_mma(
    const float* __restrict__ A, const float* __restrict__ W,
    float* __restrict__ Cbase, const float* __restrict__ res,
    int Nout, int K, int kLen)
{
    extern __shared__ float sm[];
    float* Asm = sm;                 // 3 * T_STG
    float* Bsm = sm + 3 * T_STG;     // 3 * T_STG
    uint32_t sA = smem_u32(Asm);
    uint32_t sB = smem_u32(Bsm);

    int tid = threadIdx.x;
    int warp = tid >> 5, lane = tid & 31;
    int bm = blockIdx.y * BM, bn = blockIdx.x * BN;
    int k0base = blockIdx.z * kLen;
    float* C = Cbase + (size_t)blockIdx.z * ((size_t)ML * Nout);
    int wm = (warp >> 2) * 64;   // warp M offset in tile
    int wn = (warp & 3) * 32;    // warp N offset in tile

    // ldmatrix per-lane source offsets (within a stage buffer, in bytes)
    uint32_t aLaneOff = (((uint32_t)(wm + (lane & 15)) * KP) + ((lane >> 4) << 2)) * 4;
    uint32_t bLaneOff = (((uint32_t)(wn + (((lane >> 4) & 1) << 3) + (lane & 7)) * KP)
                         + (((lane >> 3) & 1) << 2)) * 4;

    float d[4][4][4];
    #pragma unroll
    for (int i = 0; i < 4; i++)
        #pragma unroll
        for (int j = 0; j < 4; j++)
            #pragma unroll
            for (int f = 0; f < 4; f++) d[i][j][f] = 0.f;

    int NS = kLen / BK;

    // stage loader: 1024 cp16 tasks for A, 1024 for B -> 8 per thread
    auto load_stage = [&](int s, int buf) {
        int k0 = k0base + s * BK;
        uint32_t aoff = sA + buf * T_STG * 4;
        uint32_t boff = sB + buf * T_STG * 4;
        #pragma unroll
        for (int i = 0; i < 4; i++) {
            int id = tid + i * 256;
            int r = id >> 3, seg = id & 7;
            cp16(aoff + (r * KP + seg * 4) * 4,
                 A + (size_t)(bm + r) * K + k0 + seg * 4, 16);
        }
        #pragma unroll
        for (int i = 0; i < 4; i++) {
            int id = tid + i * 256;
            int r = id >> 3, seg = id & 7;
            int ok = (bn + r) < Nout;
            cp16(boff + (r * KP + seg * 4) * 4,
                 W + (size_t)(ok ? (bn + r) : 0) * K + k0 + seg * 4, ok ? 16 : 0);
        }
        CP_COMMIT();
    };

    auto compute = [&](int buf) {
        uint32_t aBuf = sA + buf * T_STG * 4 + aLaneOff;
        uint32_t bBuf = sB + buf * T_STG * 4 + bLaneOff;
        #pragma unroll
        for (int ks = 0; ks < BK; ks += 8) {
            uint32_t af[4][4], bf[4][2];
            #pragma unroll
            for (int mt = 0; mt < 4; mt++)
                ldsm_x4(af[mt][0], af[mt][1], af[mt][2], af[mt][3],
                        aBuf + (uint32_t)(mt * 16 * KP + ks) * 4);
            #pragma unroll
            for (int np = 0; np < 2; np++)
                ldsm_x4(bf[2*np][0], bf[2*np][1], bf[2*np+1][0], bf[2*np+1][1],
                        bBuf + (uint32_t)(np * 16 * KP + ks) * 4);
            // round W fragments to tf32 (idempotent wrt pre-rounded inputs)
            #pragma unroll
            for (int nt = 0; nt < 4; nt++) {
                bf[nt][0] = tf32u(__uint_as_float(bf[nt][0]));
                bf[nt][1] = tf32u(__uint_as_float(bf[nt][1]));
            }
            #pragma unroll
            for (int mt = 0; mt < 4; mt++)
                #pragma unroll
                for (int nt = 0; nt < 4; nt++)
                    mma_tf32(d[mt][nt], af[mt], bf[nt]);
        }
    };

    load_stage(0, 0);
    load_stage(1, 1);
    for (int s = 0; s < NS; s++) {
        if (s + 1 < NS) { CP_WAIT(1); } else { CP_WAIT(0); }
        __syncthreads();
        if (s + 2 < NS) load_stage(s + 2, (s + 2) % 3);
        compute(s % 3);
    }

    // epilogue
    int row = lane >> 2, kq = lane & 3;
    #pragma unroll
    for (int mt = 0; mt < 4; mt++) {
        int r0 = bm + wm + mt * 16 + row;
        #pragma unroll
        for (int nt = 0; nt < 4; nt++) {
            int c0 = bn + wn + nt * 8 + kq * 2;
            if (c0 < Nout) {
                float2 v0 = make_float2(d[mt][nt][0], d[mt][nt][1]);
                float2 v1 = make_float2(d[mt][nt][2], d[mt][nt][3]);
                if (res) {
                    float2 q0 = *(const float2*)(res + (size_t)r0 * Nout + c0);
                    float2 q1 = *(const float2*)(res + (size_t)(r0 + 8) * Nout + c0);
                    v0.x += q0.x; v0.y += q0.y;
                    v1.x += q1.x; v1.y += q1.y;
                }
                *(float2*)(C + (size_t)r0 * Nout + c0) = v0;
                *(float2*)(C + (size_t)(r0 + 8) * Nout + c0) = v1;
            }
        }
    }
}

// ---------------- split-K reduce + residual --------------------------------
__global__ void reduce4_kernel(const float* __restrict__ u, float* __restrict__ out) {
    int i = blockIdx.x * 256 + threadIdx.x;   // < ML*DMd/4
    const float4* p0 = (const float4*)g_pt;
    const float4* p1 = p0 + (size_t)ML * DMd / 4;
    const float4* p2 = p1 + (size_t)ML * DMd / 4;
    const float4* p3 = p2 + (size_t)ML * DMd / 4;
    float4 a = p0[i], b = p1[i], c = p2[i], e = p3[i];
    float4 r = ((const float4*)u)[i];
    float4 o;
    o.x = a.x + b.x + c.x + e.x + r.x;
    o.y = a.y + b.y + c.y + e.y + r.y;
    o.z = a.z + b.z + c.z + e.z + r.z;
    o.w = a.w + b.w + c.w + e.w + r.w;
    ((float4*)out)[i] = o;
}

// ---------------- helpers ----------------
__device__ __forceinline__ float block_sum_256(float v) {
    #pragma unroll
    for (int o = 16; o; o >>= 1) v += __shfl_xor_sync(0xffffffffu, v, o);
    __shared__ float sh[8];
    int w = threadIdx.x >> 5;
    if ((threadIdx.x & 31) == 0) sh[w] = v;
    __syncthreads();
    float s = 0.f;
    #pragma unroll
    for (int i = 0; i < 8; i++) s += sh[i];
    return s;
}
__device__ __forceinline__ float siluf(float x) { return x / (1.f + expf(-x)); }
__device__ __forceinline__ float tf32r(float x) {
    return __uint_as_float(tf32u(x));
}

// ---------------- 1) input RMSNorm: u (ML,2048) -> g_hs (tf32) -------------
__global__ void rmsnorm_in_kernel(const float* __restrict__ u,
                                  const float* __restrict__ w) {
    int row = blockIdx.x;
    const float* x = u + (size_t)row * DMd;
    float* o = g_hs + (size_t)row * DMd;
    int t = threadIdx.x;
    float v[8];
    float ss = 0.f;
    #pragma unroll
    for (int i = 0; i < 2; i++) {
        float4 p = *(const float4*)(x + t * 4 + i * 1024);
        v[i*4+0]=p.x; v[i*4+1]=p.y; v[i*4+2]=p.z; v[i*4+3]=p.w;
        ss += p.x*p.x + p.y*p.y + p.z*p.z + p.w*p.w;
    }
    float total = block_sum_256(ss);
    float scale = rsqrtf(total / (float)DMd + EPSf);
    #pragma unroll
    for (int i = 0; i < 2; i++) {
        int c = t * 4 + i * 1024;
        float4 q;
        q.x = tf32r(w[c+0] * v[i*4+0] * scale);
        q.y = tf32r(w[c+1] * v[i*4+1] * scale);
        q.z = tf32r(w[c+2] * v[i*4+2] * scale);
        q.w = tf32r(w[c+3] * v[i*4+3] * scale);
        *(float4*)(o + c) = q;
    }
}

// ---------------- 3) causal depthwise conv (K=4) + SiLU --------------------
__global__ void conv_silu_kernel(const float* __restrict__ conv_w,
                                 const float* __restrict__ conv_b) {
    int c  = blockIdx.x * 128 + threadIdx.x;   // 0..4223
    int bl = blockIdx.y;                        // 0..ML-1
    int b = bl >> 11;
    int l = bl & 2047;
    float acc = conv_b[c];
    #pragma unroll
    for (int k = 0; k < 4; k++) {
        int ls = l + k - 3;
        if (ls >= 0)
            acc += g_zx[(size_t)((b << 11) + ls) * PROJC + DIi + c] * conv_w[k * CONVC + c];
    }
    g_xc[(size_t)bl * CONVC + c] = siluf(acc);
}

// ---------------- 4) dt = softplus(raw + bias); dA = exp(-exp(Alog)*dt) ----
__global__ void dt_kernel(const float* __restrict__ dt_bias,
                          const float* __restrict__ A_log) {
    int idx = blockIdx.x * 256 + threadIdx.x;
    int m = idx >> 6;
    int h = idx & 63;
    float x = g_zx[(size_t)m * PROJC + DIi + CONVC + h] + dt_bias[h];
    float sp = (x > 20.f) ? x : log1pf(expf(x));
    g_dt[idx] = sp;
    g_dA[idx] = expf(-expf(A_log[h]) * sp);
}

// ---------------- 5) sequential selective scan (512 thr: 8 n/thread) -------
__global__ __launch_bounds__(512) void scan_kernel(const float* __restrict__ Dp) {
    int hh = blockIdx.x, b = blockIdx.y;
    int tid = threadIdx.x;
    int q = tid & 7;         // 0..7
    int p = tid >> 3;        // 0..63
    int n0 = q << 3;         // 8 n's per thread

    __shared__ float sB[32][64], sC[32][64], sx[32][64];
    __shared__ float sdt[32], sdA[32];

    float h[8];
    #pragma unroll
    for (int i = 0; i < 8; i++) h[i] = 0.f;
    float Dh = Dp[hh];

    for (int l0 = 0; l0 < Ll; l0 += 32) {
        __syncthreads();
        for (int j = tid; j < 32 * 64; j += 512) {
            int s = j >> 6, n = j & 63;
            size_t rb = (size_t)((b << 11) + l0 + s) * CONVC;
            sB[s][n] = g_xc[rb + DIi + n];
            sC[s][n] = g_xc[rb + DIi + Nst + n];
            sx[s][n] = g_xc[rb + (hh << 6) + n];
        }
        if (tid < 32) {
            int m = (b << 11) + l0 + tid;
            sdt[tid] = g_dt[m * Hh + hh];
            sdA[tid] = g_dA[m * Hh + hh];
        }
        __syncthreads();

        for (int s = 0; s < 32; s++) {
            float dAv = sdA[s], dtv = sdt[s];
            float x = sx[s][p];
            float dtx = dtv * x;
            float4 Bv0 = *(const float4*)&sB[s][n0];
            float4 Bv1 = *(const float4*)&sB[s][n0 + 4];
            float4 Cv0 = *(const float4*)&sC[s][n0];
            float4 Cv1 = *(const float4*)&sC[s][n0 + 4];
            float a0, a1;
            h[0] = dAv*h[0] + dtx*Bv0.x; a0  = h[0]*Cv0.x;
            h[1] = dAv*h[1] + dtx*Bv0.y; a0 += h[1]*Cv0.y;
            h[2] = dAv*h[2] + dtx*Bv0.z; a0 += h[2]*Cv0.z;
            h[3] = dAv*h[3] + dtx*Bv0.w; a0 += h[3]*Cv0.w;
            h[4] = dAv*h[4] + dtx*Bv1.x; a1  = h[4]*Cv1.x;
            h[5] = dAv*h[5] + dtx*Bv1.y; a1 += h[5]*Cv1.y;
            h[6] = dAv*h[6] + dtx*Bv1.z; a1 += h[6]*Cv1.z;
            h[7] = dAv*h[7] + dtx*Bv1.w; a1 += h[7]*Cv1.w;
            float a = a0 + a1;
            a += __shfl_xor_sync(0xffffffffu, a, 1);
            a += __shfl_xor_sync(0xffffffffu, a, 2);
            a += __shfl_xor_sync(0xffffffffu, a, 4);
            if (q == 0) {
                size_t ob = (size_t)((b << 11) + l0 + s) * DIi + (hh << 6);
                g_y[ob + p] = a + Dh * x;
            }
        }
    }
}

// ---------------- 6) gated RMSNorm -> g_nr (tf32) --------------------------
__global__ void gated_norm_kernel(const float* __restrict__ nw) {
    int row = blockIdx.x;
    const float* yr = g_y + (size_t)row * DIi;
    const float* zr = g_zx + (size_t)row * PROJC;
    float* o = g_nr + (size_t)row * DIi;
    int t = threadIdx.x;
    float v[16];
    float ss = 0.f;
    #pragma unroll
    for (int i = 0; i < 4; i++) {
        int c = t * 4 + i * 1024;
        float4 yv = *(const float4*)(yr + c);
        float4 zv = *(const float4*)(zr + c);
        float a0 = yv.x * siluf(zv.x);
        float a1 = yv.y * siluf(zv.y);
        float a2 = yv.z * siluf(zv.z);
        float a3 = yv.w * siluf(zv.w);
        v[i*4+0]=a0; v[i*4+1]=a1; v[i*4+2]=a2; v[i*4+3]=a3;
        ss += a0*a0 + a1*a1 + a2*a2 + a3*a3;
    }
    float total = block_sum_256(ss);
    float scale = rsqrtf(total / (float)DIi + EPSf);
    #pragma unroll
    for (int i = 0; i < 4; i++) {
        int c = t * 4 + i * 1024;
        float4 qv;
        qv.x = tf32r(nw[c+0] * v[i*4+0] * scale);
        qv.y = tf32r(nw[c+1] * v[i*4+1] * scale);
        qv.z = tf32r(nw[c+2] * v[i*4+2] * scale);
        qv.w = tf32r(nw[c+3] * v[i*4+3] * scale);
        *(float4*)(o + c) = qv;
    }
}

// ---------------- launcher -------------------------------------------------
extern "C" void kernel_launch(void* const* d_in, const int* in_sizes, int n_in,
                              void* d_out, int out_size) {
    const float* u          = (const float*)d_in[0];
    const float* ln_w       = (const float*)d_in[1];
    const float* in_proj_w  = (const float*)d_in[2];
    const float* conv_w     = (const float*)d_in[3];
    const float* conv_b     = (const float*)d_in[4];
    const float* dt_bias    = (const float*)d_in[5];
    const float* A_log      = (const float*)d_in[6];
    const float* Dp         = (const float*)d_in[7];
    const float* norm_w     = (const float*)d_in[8];
    const float* out_proj_w = (const float*)d_in[9];
    float* out = (float*)d_out;

    float *hs_p, *zx_p, *nr_p, *pt_p;
    cudaGetSymbolAddress((void**)&hs_p, g_hs);
    cudaGetSymbolAddress((void**)&zx_p, g_zx);
    cudaGetSymbolAddress((void**)&nr_p, g_nr);
    cudaGetSymbolAddress((void**)&pt_p, g_pt);

    cudaFuncSetAttribute(gemm_mma, cudaFuncAttributeMaxDynamicSharedMemorySize, SMEM_GEMM);

    // 1) input rmsnorm (tf32-rounded output)
    rmsnorm_in_kernel<<<ML, 256>>>(u, ln_w);

    // 2) in_proj: (4096,2048) x (8384,2048)^T -> (4096,8384); W rounded in-kernel
    {
        dim3 grid((PROJC + BN - 1) / BN, ML / BM, 1);
        gemm_mma<<<grid, 256, SMEM_GEMM>>>(hs_p, in_proj_w, zx_p, nullptr, PROJC, DMd, DMd);
    }

    // 3) conv + silu
    {
        dim3 grid(CONVC / 128, ML);
        conv_silu_kernel<<<grid, 128>>>(conv_w, conv_b);
    }

    // 4) dt / dA
    dt_kernel<<<(ML * Hh) / 256, 256>>>(dt_bias, A_log);

    // 5) scan (512 threads, 8 n per thread)
    {
        dim3 grid(Hh, Bb);
        scan_kernel<<<grid, 512>>>(Dp);
    }

    // 6) gated rmsnorm (tf32-rounded output)
    gated_norm_kernel<<<ML, 256>>>(norm_w);

    // 7) out_proj split-K=4: (4096,4096) x (2048,4096)^T -> 4 partials
    {
        dim3 grid(DMd / BN, ML / BM, 4);
        gemm_mma<<<grid, 256, SMEM_GEMM>>>(nr_p, out_proj_w, pt_p, nullptr, DMd, DIi, DIi / 4);
    }

    // 8) reduce partials + residual -> out
    reduce4_kernel<<<(ML * DMd / 4) / 256, 256>>>(u, out);
}